// round 10
// baseline (speedup 1.0000x reference)
#include <cuda_runtime.h>
#include <cstdint>

// Input order (metadata):
// 0 exposure_params [200] f32 | 1 vignetting_params [4,3,5] f32
// 2 color_params [200,8] f32  | 3 crf_params [4,3,4] f32
// 4 rgb_in [H,W,3] f32        | 5 pixel_coords [H,W,2] f32 (unused; reconstructed)
// 6 resolution_w i32 | 7 resolution_h i32 | 8 camera_idx i32 | 9 frame_idx i32

// Shared-memory folded parameter layout (same indices as prior __constant__ blob):
//  0..2  PX[3]  (= -2*cx)        3..5  PY[3] (= -2*cy)     6..8  PC[3] (= cx^2+cy^2)
//  9..11 A1[3]  (= a1*inv)      12..14 A2[3] (= a2*inv^2) 15..17 A3[3] (= a3*inv^3)
// 18..26 M[9]   exposure-folded color matrix (row-major)
// 27..29 G[3]   gamma
// 30..32 KA[3] (= 1+C0)  33..35 KB[3] (= C1-C0)  36..38 KC[3] (= -C1)
//        [CRF refold: y + y(1-y)(C0+C1 y) == y*(KA + y*(KB + y*KC)),
//         C0=q1+q3, C1=q2-q3]
// 39     crf_on

__device__ __forceinline__ float mufu_lg2(float x) {
    float r; asm("lg2.approx.f32 %0, %1;" : "=f"(r) : "f"(x)); return r;
}
__device__ __forceinline__ float mufu_ex2(float x) {
    float r; asm("ex2.approx.f32 %0, %1;" : "=f"(r) : "f"(x)); return r;
}

// Per-pixel pipeline; sp = smem param block, ty = per-row hoisted quadratic.
__device__ __forceinline__ void process_pixel(const float* __restrict__ sp,
                                              const float* __restrict__ ty,
                                              float x, bool crf_on,
                                              float& r0, float& r1, float& r2c) {
    float c0 = r0, c1 = r1, c2 = r2c;

    // vignetting: r2 = x^2 + PX*x + ty ; vig = 1 + r2*(A1 + r2*(A2 + r2*A3))
    {
        const float r2 = fmaf(x, x + sp[0], ty[0]);
        float h = fmaf(r2, sp[15], sp[12]);
        h = fmaf(r2, h, sp[9]);
        c0 = fmaf(c0, r2 * h, c0);
    }
    {
        const float r2 = fmaf(x, x + sp[1], ty[1]);
        float h = fmaf(r2, sp[16], sp[13]);
        h = fmaf(r2, h, sp[10]);
        c1 = fmaf(c1, r2 * h, c1);
    }
    {
        const float r2 = fmaf(x, x + sp[2], ty[2]);
        float h = fmaf(r2, sp[17], sp[14]);
        h = fmaf(r2, h, sp[11]);
        c2 = fmaf(c2, r2 * h, c2);
    }

    // 3x3 color matrix (exposure folded in)
    float o0 = fmaf(sp[18], c0, fmaf(sp[19], c1, sp[20] * c2));
    float o1 = fmaf(sp[21], c0, fmaf(sp[22], c1, sp[23] * c2));
    float o2 = fmaf(sp[24], c0, fmaf(sp[25], c1, sp[26] * c2));

    // CRF gamma + perturbation (refolded cubic Horner: y*(KA + y*(KB + y*KC)))
    if (crf_on) {
        {
            const float xc = __saturatef(o0);
            const float yv = mufu_ex2(sp[27] * mufu_lg2(xc)); // xc=0 -> -inf -> 0, correct
            o0 = yv * fmaf(yv, fmaf(yv, sp[36], sp[33]), sp[30]);
        }
        {
            const float xc = __saturatef(o1);
            const float yv = mufu_ex2(sp[28] * mufu_lg2(xc));
            o1 = yv * fmaf(yv, fmaf(yv, sp[37], sp[34]), sp[31]);
        }
        {
            const float xc = __saturatef(o2);
            const float yv = mufu_ex2(sp[29] * mufu_lg2(xc));
            o2 = yv * fmaf(yv, fmaf(yv, sp[38], sp[35]), sp[32]);
        }
    }

    r0 = o0; r1 = o1; r2c = o2;
}

__global__ void __launch_bounds__(256, 6) ppisp_fused(
    const float* __restrict__ exposure,
    const float* __restrict__ vig,
    const float* __restrict__ color,
    const float* __restrict__ crf,
    const float* __restrict__ in,
    float* __restrict__ out,
    const int* __restrict__ rw,
    const int* __restrict__ rh,
    const int* __restrict__ cam,
    const int* __restrict__ frm,
    unsigned npix) {
    __shared__ float sp[40];
    __shared__ unsigned sW, sShift, sMask, sPow2;

    // ---- per-block fold (thread 0; cold branch, spills OK) ----
    if (threadIdx.x == 0) {
        const int f = frm[0];
        const int c = cam[0];
        const unsigned Wu = (unsigned)rw[0];
        const float Wf = (float)rw[0];
        const float Hf = (float)rh[0];

        sW = Wu;
        const bool pow2 = (Wu != 0u) && ((Wu & (Wu - 1u)) == 0u);
        sPow2 = pow2 ? 1u : 0u;
        sMask = Wu - 1u;
        unsigned s = 0;
        if (pow2) { unsigned w = Wu; while (w > 1u) { w >>= 1; s++; } }
        sShift = s;

        const float e = (f >= 0) ? expf(exposure[f]) : 1.0f;
        const float norm2 = (0.5f * Wf) * (0.5f * Wf) + (0.5f * Hf) * (0.5f * Hf);
        const float inv = 1.0f / norm2;

        for (int ch = 0; ch < 3; ch++) {
            float PX = 0.f, PY = 0.f, PC = 0.f, A1 = 0.f, A2 = 0.f, A3 = 0.f;
            float G = 1.f, KA = 1.f, KB = 0.f, KC = 0.f;
            if (c >= 0) {
                const float* vp = vig + ((size_t)c * 3 + ch) * 5;
                const float cx = (0.5f + vp[0]) * Wf;
                const float cy = (0.5f + vp[1]) * Hf;
                PX = -2.0f * cx;
                PY = -2.0f * cy;
                PC = fmaf(cx, cx, cy * cy);
                A1 = vp[2] * inv;
                A2 = vp[3] * inv * inv;
                A3 = vp[4] * inv * inv * inv;
                const float* q = crf + ((size_t)c * 3 + ch) * 4;
                G  = expf(q[0]);
                const float C0 = q[1] + q[3];
                const float C1 = q[2] - q[3];
                KA = 1.0f + C0;
                KB = C1 - C0;
                KC = -C1;
            }
            sp[0 + ch]  = PX;
            sp[3 + ch]  = PY;
            sp[6 + ch]  = PC;
            sp[9 + ch]  = A1;
            sp[12 + ch] = A2;
            sp[15 + ch] = A3;
            sp[27 + ch] = G;
            sp[30 + ch] = KA;
            sp[33 + ch] = KB;
            sp[36 + ch] = KC;
        }

        float M[9];
        if (f >= 0) {
            const float* p = color + (size_t)f * 8;
            M[0] = 1.0f + p[0]; M[1] = p[1];        M[2] = p[2];
            M[3] = p[3];        M[4] = 1.0f + p[4]; M[5] = p[5];
            M[6] = p[6];        M[7] = p[7];        M[8] = 1.0f;
        } else {
            M[0] = 1.f; M[1] = 0.f; M[2] = 0.f;
            M[3] = 0.f; M[4] = 1.f; M[5] = 0.f;
            M[6] = 0.f; M[7] = 0.f; M[8] = 1.f;
        }
        for (int i = 0; i < 9; i++) sp[18 + i] = M[i] * e;

        sp[39] = (c >= 0) ? 1.0f : 0.0f;
    }
    __syncthreads();

    // ---- hot path (identical math to R9) ----
    const unsigned gid = blockIdx.x * blockDim.x + threadIdx.x;
    const unsigned p0 = gid * 4u;
    if (p0 >= npix) return;

    const unsigned W = sW;
    const bool crf_on = (sp[39] > 0.5f);

    unsigned row, col;
    if (sPow2) {                   // uniform branch; W=4096 -> shift/mask, no IDIV
        row = p0 >> sShift;
        col = p0 & sMask;
    } else {
        row = p0 / W;
        col = p0 - row * W;
    }

    if (p0 + 3u < npix && col + 3u < W) {
        // fast path: 4 pixels in one row (always taken when W % 4 == 0)
        const float4* in4 = reinterpret_cast<const float4*>(in);
        float4* out4 = reinterpret_cast<float4*>(out);
        const size_t base = (size_t)gid * 3u;
        float4 A = in4[base + 0];
        float4 B = in4[base + 1];
        float4 C = in4[base + 2];

        const float y = (float)row + 0.5f;
        const float x0 = (float)col + 0.5f;

        float ty[3];
#pragma unroll
        for (int ch = 0; ch < 3; ch++)
            ty[ch] = fmaf(y, y + sp[3 + ch], sp[6 + ch]);

        process_pixel(sp, ty, x0 + 0.f, crf_on, A.x, A.y, A.z);
        process_pixel(sp, ty, x0 + 1.f, crf_on, A.w, B.x, B.y);
        process_pixel(sp, ty, x0 + 2.f, crf_on, B.z, B.w, C.x);
        process_pixel(sp, ty, x0 + 3.f, crf_on, C.y, C.z, C.w);

        __stcs(&out4[base + 0], A);
        __stcs(&out4[base + 1], B);
        __stcs(&out4[base + 2], C);
    } else {
        // generic tail / row-wrap path
        unsigned rr = row, cc = col;
        const unsigned pend = (p0 + 4u < npix) ? (p0 + 4u) : npix;
        for (unsigned p = p0; p < pend; p++) {
            float r = in[(size_t)p * 3 + 0];
            float g = in[(size_t)p * 3 + 1];
            float b = in[(size_t)p * 3 + 2];
            const float yy = (float)rr + 0.5f;
            float ty[3];
#pragma unroll
            for (int ch = 0; ch < 3; ch++)
                ty[ch] = fmaf(yy, yy + sp[3 + ch], sp[6 + ch]);
            process_pixel(sp, ty, (float)cc + 0.5f, crf_on, r, g, b);
            out[(size_t)p * 3 + 0] = r;
            out[(size_t)p * 3 + 1] = g;
            out[(size_t)p * 3 + 2] = b;
            cc++;
            if (cc == W) { cc = 0u; rr++; }
        }
    }
}

extern "C" void kernel_launch(void* const* d_in, const int* in_sizes, int n_in,
                              void* d_out, int out_size) {
    const float* exposure = (const float*)d_in[0];
    const float* vig      = (const float*)d_in[1];
    const float* color    = (const float*)d_in[2];
    const float* crf      = (const float*)d_in[3];
    const float* rgb_in   = (const float*)d_in[4];
    // d_in[5] = pixel_coords, intentionally unused (reconstructed analytically)
    const int* rw  = (const int*)d_in[6];
    const int* rh  = (const int*)d_in[7];
    const int* cam = (const int*)d_in[8];
    const int* frm = (const int*)d_in[9];
    float* out = (float*)d_out;

    const unsigned npix = (unsigned)(in_sizes[4] / 3);
    const unsigned nthreads = (npix + 3u) / 4u;
    const unsigned blocks = (nthreads + 255u) / 256u;

    // single graph node: per-block smem fold + hot loop
    ppisp_fused<<<blocks, 256>>>(exposure, vig, color, crf, rgb_in, out,
                                 rw, rh, cam, frm, npix);
}

// round 11
// speedup vs baseline: 1.1852x; 1.1852x over previous
#include <cuda_runtime.h>
#include <cstdint>

// Input order (metadata):
// 0 exposure_params [200] f32 | 1 vignetting_params [4,3,5] f32
// 2 color_params [200,8] f32  | 3 crf_params [4,3,4] f32
// 4 rgb_in [H,W,3] f32        | 5 pixel_coords [H,W,2] f32 (unused; reconstructed)
// 6 resolution_w i32 | 7 resolution_h i32 | 8 camera_idx i32 | 9 frame_idx i32

// Shared param block layout (indices):
//  0..2  PX[3] (=-2cx)   3..5 PY[3] (=-2cy)   6..8 PC[3] (=cx^2+cy^2)
//  9..11 A1[3] (=a1*inv) 12..14 A2[3] (=a2*inv^2) 15..17 A3[3] (=a3*inv^3)
// 18..26 M[9] exposure-folded color matrix (row-major)
// 27..29 G[3] gamma
// 30..32 KA[3] (=1+C0) 33..35 KB[3] (=C1-C0) 36..38 KC[3] (=-C1)
//        [y + y(1-y)(C0+C1 y) == y*(KA + y*(KB + y*KC)), C0=q1+q3, C1=q2-q3]
// 39     crf_on

__device__ __forceinline__ float mufu_lg2(float x) {
    float r; asm("lg2.approx.f32 %0, %1;" : "=f"(r) : "f"(x)); return r;
}
__device__ __forceinline__ float mufu_ex2(float x) {
    float r; asm("ex2.approx.f32 %0, %1;" : "=f"(r) : "f"(x)); return r;
}

// Opaque shared vector load: asm result registers cannot be rematerialized by
// ptxas, so params are loaded from smem EXACTLY ONCE and stay register-resident
// (the R6/R10 failure was ~120 per-use LDS per thread; this makes it 10).
__device__ __forceinline__ float4 lds4(const float* p) {
    float4 v;
    uint32_t a = (uint32_t)__cvta_generic_to_shared(p);
    asm("ld.shared.v4.f32 {%0,%1,%2,%3}, [%4];"
        : "=f"(v.x), "=f"(v.y), "=f"(v.z), "=f"(v.w) : "r"(a));
    return v;
}

struct FP {
    float PX[3], PY[3], PC[3];
    float A1[3], A2[3], A3[3];
    float M[9];
    float G[3], KA[3], KB[3], KC[3];
    bool  crf_on;
};

__device__ __forceinline__ void load_fp(const float* sp, FP& P) {
    float4 v0 = lds4(sp + 0);
    float4 v1 = lds4(sp + 4);
    float4 v2 = lds4(sp + 8);
    float4 v3 = lds4(sp + 12);
    float4 v4 = lds4(sp + 16);
    float4 v5 = lds4(sp + 20);
    float4 v6 = lds4(sp + 24);
    float4 v7 = lds4(sp + 28);
    float4 v8 = lds4(sp + 32);
    float4 v9 = lds4(sp + 36);
    P.PX[0]=v0.x; P.PX[1]=v0.y; P.PX[2]=v0.z;
    P.PY[0]=v0.w; P.PY[1]=v1.x; P.PY[2]=v1.y;
    P.PC[0]=v1.z; P.PC[1]=v1.w; P.PC[2]=v2.x;
    P.A1[0]=v2.y; P.A1[1]=v2.z; P.A1[2]=v2.w;
    P.A2[0]=v3.x; P.A2[1]=v3.y; P.A2[2]=v3.z;
    P.A3[0]=v3.w; P.A3[1]=v4.x; P.A3[2]=v4.y;
    P.M[0]=v4.z;  P.M[1]=v4.w;  P.M[2]=v5.x;
    P.M[3]=v5.y;  P.M[4]=v5.z;  P.M[5]=v5.w;
    P.M[6]=v6.x;  P.M[7]=v6.y;  P.M[8]=v6.z;
    P.G[0]=v6.w;  P.G[1]=v7.x;  P.G[2]=v7.y;
    P.KA[0]=v7.z; P.KA[1]=v7.w; P.KA[2]=v8.x;
    P.KB[0]=v8.y; P.KB[1]=v8.z; P.KB[2]=v8.w;
    P.KC[0]=v9.x; P.KC[1]=v9.y; P.KC[2]=v9.z;
    P.crf_on = (v9.w > 0.5f);
}

__device__ __forceinline__ void process_pixel(const FP& P,
                                              const float* __restrict__ ty,
                                              float x,
                                              float& r0, float& r1, float& r2c) {
    float c0 = r0, c1 = r1, c2 = r2c;

    // vignetting: r2 = x^2 + PX*x + ty ; vig = 1 + r2*(A1 + r2*(A2 + r2*A3))
    {
        const float r2 = fmaf(x, x + P.PX[0], ty[0]);
        float h = fmaf(r2, P.A3[0], P.A2[0]);
        h = fmaf(r2, h, P.A1[0]);
        c0 = fmaf(c0, r2 * h, c0);
    }
    {
        const float r2 = fmaf(x, x + P.PX[1], ty[1]);
        float h = fmaf(r2, P.A3[1], P.A2[1]);
        h = fmaf(r2, h, P.A1[1]);
        c1 = fmaf(c1, r2 * h, c1);
    }
    {
        const float r2 = fmaf(x, x + P.PX[2], ty[2]);
        float h = fmaf(r2, P.A3[2], P.A2[2]);
        h = fmaf(r2, h, P.A1[2]);
        c2 = fmaf(c2, r2 * h, c2);
    }

    // 3x3 color matrix (exposure folded in)
    float o0 = fmaf(P.M[0], c0, fmaf(P.M[1], c1, P.M[2] * c2));
    float o1 = fmaf(P.M[3], c0, fmaf(P.M[4], c1, P.M[5] * c2));
    float o2 = fmaf(P.M[6], c0, fmaf(P.M[7], c1, P.M[8] * c2));

    // CRF gamma + perturbation (refolded cubic Horner: y*(KA + y*(KB + y*KC)))
    if (P.crf_on) {
        {
            const float xc = __saturatef(o0);
            const float yv = mufu_ex2(P.G[0] * mufu_lg2(xc)); // xc=0 -> -inf -> 0, correct
            o0 = yv * fmaf(yv, fmaf(yv, P.KC[0], P.KB[0]), P.KA[0]);
        }
        {
            const float xc = __saturatef(o1);
            const float yv = mufu_ex2(P.G[1] * mufu_lg2(xc));
            o1 = yv * fmaf(yv, fmaf(yv, P.KC[1], P.KB[1]), P.KA[1]);
        }
        {
            const float xc = __saturatef(o2);
            const float yv = mufu_ex2(P.G[2] * mufu_lg2(xc));
            o2 = yv * fmaf(yv, fmaf(yv, P.KC[2], P.KB[2]), P.KA[2]);
        }
    }

    r0 = o0; r1 = o1; r2c = o2;
}

__global__ void __launch_bounds__(256) ppisp_fused(
    const float* __restrict__ exposure,
    const float* __restrict__ vig,
    const float* __restrict__ color,
    const float* __restrict__ crf,
    const float* __restrict__ in,
    float* __restrict__ out,
    const int* __restrict__ rw,
    const int* __restrict__ rh,
    const int* __restrict__ cam,
    const int* __restrict__ frm,
    unsigned npix) {
    __shared__ __align__(16) float sp[40];
    __shared__ unsigned sW, sShift, sMask, sPow2;

    // ---- warp-parallel fold: lanes 0..13 each own a small disjoint slice.
    // Per-lane register footprint ~12 regs (no serial thread-0 array code,
    // which is what blew the register watermark in R6/R10).
    if (threadIdx.x < 32) {
        const int lane = threadIdx.x;
        const int f = frm[0];
        const int c = cam[0];
        const unsigned Wu = (unsigned)rw[0];
        const float Wf = (float)Wu;
        const float Hf = (float)rh[0];

        if (lane < 3) {
            // per-channel vignetting + CRF fold
            const int ch = lane;
            float PX = 0.f, PY = 0.f, PC = 0.f, A1 = 0.f, A2 = 0.f, A3 = 0.f;
            float G = 1.f, KA = 1.f, KB = 0.f, KC = 0.f;
            if (c >= 0) {
                const float norm2 = (0.5f * Wf) * (0.5f * Wf) + (0.5f * Hf) * (0.5f * Hf);
                const float inv = 1.0f / norm2;
                const float* vp = vig + ((size_t)c * 3 + ch) * 5;
                const float cx = (0.5f + vp[0]) * Wf;
                const float cy = (0.5f + vp[1]) * Hf;
                PX = -2.0f * cx;
                PY = -2.0f * cy;
                PC = fmaf(cx, cx, cy * cy);
                A1 = vp[2] * inv;
                A2 = vp[3] * inv * inv;
                A3 = vp[4] * inv * inv * inv;
                const float* q = crf + ((size_t)c * 3 + ch) * 4;
                G  = expf(q[0]);
                const float C0 = q[1] + q[3];
                const float C1 = q[2] - q[3];
                KA = 1.0f + C0;
                KB = C1 - C0;
                KC = -C1;
            }
            sp[0 + ch]  = PX;
            sp[3 + ch]  = PY;
            sp[6 + ch]  = PC;
            sp[9 + ch]  = A1;
            sp[12 + ch] = A2;
            sp[15 + ch] = A3;
            sp[27 + ch] = G;
            sp[30 + ch] = KA;
            sp[33 + ch] = KB;
            sp[36 + ch] = KC;
        } else if (lane >= 4 && lane < 13) {
            // one color-matrix entry per lane, exposure folded in
            const int i = lane - 4;            // 0..8, row-major
            float Mi;
            if (f >= 0) {
                if (i == 8) {
                    Mi = 1.0f;
                } else {
                    Mi = color[(size_t)f * 8 + i];
                    if (i == 0 || i == 4) Mi += 1.0f;
                }
                const float e = expf(exposure[f]);
                Mi *= e;
            } else {
                Mi = (i == 0 || i == 4 || i == 8) ? 1.0f : 0.0f;
            }
            sp[18 + i] = Mi;
        } else if (lane == 13) {
            // scalars + flags
            sW = Wu;
            const bool pow2 = (Wu != 0u) && ((Wu & (Wu - 1u)) == 0u);
            sPow2 = pow2 ? 1u : 0u;
            sMask = Wu - 1u;
            unsigned s = 0;
            if (pow2) { unsigned w = Wu; while (w > 1u) { w >>= 1; s++; } }
            sShift = s;
            sp[39] = (c >= 0) ? 1.0f : 0.0f;
        }
    }
    __syncthreads();

    const unsigned gid = blockIdx.x * blockDim.x + threadIdx.x;
    const unsigned p0 = gid * 4u;
    if (p0 >= npix) return;

    // Pin all params into registers ONCE (opaque loads).
    FP P;
    load_fp(sp, P);

    const unsigned W = sW;
    unsigned row, col;
    if (sPow2) {                   // uniform branch; W=4096 -> shift/mask, no IDIV
        row = p0 >> sShift;
        col = p0 & sMask;
    } else {
        row = p0 / W;
        col = p0 - row * W;
    }

    if (p0 + 3u < npix && col + 3u < W) {
        // fast path: 4 pixels in one row (always taken when W % 4 == 0)
        const float4* in4 = reinterpret_cast<const float4*>(in);
        float4* out4 = reinterpret_cast<float4*>(out);
        const size_t base = (size_t)gid * 3u;
        float4 A = in4[base + 0];
        float4 B = in4[base + 1];
        float4 C = in4[base + 2];

        const float y = (float)row + 0.5f;
        const float x0 = (float)col + 0.5f;

        float ty[3];
#pragma unroll
        for (int ch = 0; ch < 3; ch++)
            ty[ch] = fmaf(y, y + P.PY[ch], P.PC[ch]);

        process_pixel(P, ty, x0 + 0.f, A.x, A.y, A.z);
        process_pixel(P, ty, x0 + 1.f, A.w, B.x, B.y);
        process_pixel(P, ty, x0 + 2.f, B.z, B.w, C.x);
        process_pixel(P, ty, x0 + 3.f, C.y, C.z, C.w);

        __stcs(&out4[base + 0], A);
        __stcs(&out4[base + 1], B);
        __stcs(&out4[base + 2], C);
    } else {
        // generic tail / row-wrap path
        unsigned rr = row, cc = col;
        const unsigned pend = (p0 + 4u < npix) ? (p0 + 4u) : npix;
        for (unsigned p = p0; p < pend; p++) {
            float r = in[(size_t)p * 3 + 0];
            float g = in[(size_t)p * 3 + 1];
            float b = in[(size_t)p * 3 + 2];
            const float yy = (float)rr + 0.5f;
            float ty[3];
#pragma unroll
            for (int ch = 0; ch < 3; ch++)
                ty[ch] = fmaf(yy, yy + P.PY[ch], P.PC[ch]);
            process_pixel(P, ty, (float)cc + 0.5f, r, g, b);
            out[(size_t)p * 3 + 0] = r;
            out[(size_t)p * 3 + 1] = g;
            out[(size_t)p * 3 + 2] = b;
            cc++;
            if (cc == W) { cc = 0u; rr++; }
        }
    }
}

extern "C" void kernel_launch(void* const* d_in, const int* in_sizes, int n_in,
                              void* d_out, int out_size) {
    const float* exposure = (const float*)d_in[0];
    const float* vig      = (const float*)d_in[1];
    const float* color    = (const float*)d_in[2];
    const float* crf      = (const float*)d_in[3];
    const float* rgb_in   = (const float*)d_in[4];
    // d_in[5] = pixel_coords, intentionally unused (reconstructed analytically)
    const int* rw  = (const int*)d_in[6];
    const int* rh  = (const int*)d_in[7];
    const int* cam = (const int*)d_in[8];
    const int* frm = (const int*)d_in[9];
    float* out = (float*)d_out;

    const unsigned npix = (unsigned)(in_sizes[4] / 3);
    const unsigned nthreads = (npix + 3u) / 4u;
    const unsigned blocks = (nthreads + 255u) / 256u;

    // single graph node: warp-parallel smem fold + register-pinned hot loop
    ppisp_fused<<<blocks, 256>>>(exposure, vig, color, crf, rgb_in, out,
                                 rw, rh, cam, frm, npix);
}